// round 1
// baseline (speedup 1.0000x reference)
#include <cuda_runtime.h>
#include <stdint.h>

// Problem constants (fixed shapes)
#define TT   4
#define BB   32
#define CC   384
#define NN   256          // H*W
#define NWD  12           // 384 bits / 32 = words per channel mask
#define EPSB 1e-5f
#define OUT1_ELEMS (TT*BB*CC*NN)   // 12,582,912

// Scratch (device globals; no allocation allowed)
__device__ uint32_t g_xs [TT*BB*NN*NWD];   // shortcut-LIF spikes, bits over c
__device__ uint32_t g_sq [TT*BB*NN*NWD];   // q spikes
__device__ uint32_t g_sk [TT*BB*NN*NWD];   // k spikes
__device__ uint32_t g_sv [TT*BB*NN*NWD];   // v spikes
__device__ uint32_t g_kvb[TT*BB*NWD];      // kv-LIF spikes, bits over d
__device__ float    g_wT [4][CC*CC];       // transposed weights: wT[c*C + d]

// ---------------------------------------------------------------------------
// K0: transpose the 4 weight matrices (w[d][c] -> wT[c][d])
// grid (12,12,4), block (32,32)
// ---------------------------------------------------------------------------
__global__ void transpose_kernel(const float* __restrict__ wq, const float* __restrict__ wk,
                                 const float* __restrict__ wv, const float* __restrict__ wp)
{
    __shared__ float tile[32][33];
    const float* src = (blockIdx.z == 0) ? wq : (blockIdx.z == 1) ? wk
                     : (blockIdx.z == 2) ? wv : wp;
    int d0 = blockIdx.x * 32, c0 = blockIdx.y * 32;
    tile[threadIdx.y][threadIdx.x] = src[(d0 + threadIdx.y) * CC + (c0 + threadIdx.x)];
    __syncthreads();
    g_wT[blockIdx.z][(c0 + threadIdx.y) * CC + (d0 + threadIdx.x)] = tile[threadIdx.x][threadIdx.y];
}

// ---------------------------------------------------------------------------
// K1: shortcut LIF on x -> bitpacked spikes g_xs
// grid (C/32, N/32, B), block 1024.  Phase1: coalesced load+smem transpose.
// Phase2: lane = c (for ballot), warp = n; sequential scan over T.
// ---------------------------------------------------------------------------
__global__ void lif_x_kernel(const float* __restrict__ x)
{
    __shared__ float xt[TT][32][33];
    int b = blockIdx.z, c0 = blockIdx.x << 5, n0 = blockIdx.y << 5;
    int tid = threadIdx.x;
    int cl = tid >> 5, nl = tid & 31;
#pragma unroll
    for (int t = 0; t < TT; t++)
        xt[t][cl][nl] = x[((t * BB + b) * CC + c0 + cl) * NN + n0 + nl];
    __syncthreads();
    int lane = tid & 31;   // c within word
    int wrp  = tid >> 5;   // n within tile
    float v = 0.f;
#pragma unroll
    for (int t = 0; t < TT; t++) {
        float xv = xt[t][lane][wrp];
        v += (xv - v) * 0.5f;                 // v + (x - v)/TAU, TAU=2 (exact halving)
        int s = (v - 1.0f) >= 0.f;
        uint32_t bits = __ballot_sync(0xffffffffu, s);
        if (s) v = 0.f;                        // hard reset
        if (lane == 0)
            g_xs[((t * BB + b) * NN + n0 + wrp) * NWD + (c0 >> 5)] = bits;
    }
}

// ---------------------------------------------------------------------------
// K2: fused q/k/v sparse conv1x1 + BN + LIF -> spike bits
// grid (N, B), block 384 (thread = output channel d).
// For each timestep: iterate active input channels from the bitmask and
// accumulate wT rows (exact fp32 adds of the true weight values).
// ---------------------------------------------------------------------------
__global__ void qkv_kernel(
    const float* __restrict__ qg, const float* __restrict__ qb, const float* __restrict__ qm, const float* __restrict__ qvv,
    const float* __restrict__ kg, const float* __restrict__ kb, const float* __restrict__ km, const float* __restrict__ kvv,
    const float* __restrict__ vg, const float* __restrict__ vb, const float* __restrict__ vm, const float* __restrict__ vvv)
{
    int n = blockIdx.x, b = blockIdx.y;
    int d = threadIdx.x, lane = d & 31, wrp = d >> 5;
    __shared__ uint32_t masks[TT * NWD];
    if (d < TT * NWD)
        masks[d] = g_xs[((d / NWD) * BB + b) * NN * NWD + n * NWD + (d % NWD)];
    __syncthreads();

    for (int p = 0; p < 3; p++) {
        const float* wT = g_wT[p];
        float acc[TT];
#pragma unroll
        for (int t = 0; t < TT; t++) acc[t] = 0.f;
        for (int t = 0; t < TT; t++) {
            float a = 0.f;
#pragma unroll
            for (int w = 0; w < NWD; w++) {
                uint32_t m = masks[t * NWD + w];
                while (m) {
                    int c = (w << 5) + (__ffs(m) - 1);
                    m &= m - 1;
                    a += wT[c * CC + d];
                }
            }
            acc[t] = a;
        }
        const float *gm, *bt, *mn, *vr;
        uint32_t* outp;
        if (p == 0)      { gm = qg; bt = qb; mn = qm; vr = qvv; outp = g_sq; }
        else if (p == 1) { gm = kg; bt = kb; mn = km; vr = kvv; outp = g_sk; }
        else             { gm = vg; bt = vb; mn = vm; vr = vvv; outp = g_sv; }
        float scale = gm[d] * rsqrtf(vr[d] + EPSB);
        float mean = mn[d], beta = bt[d];
        float v = 0.f;
#pragma unroll
        for (int t = 0; t < TT; t++) {
            float u = (acc[t] - mean) * scale + beta;   // BN (inference)
            v += (u - v) * 0.5f;
            int s = (v - 1.0f) >= 0.f;
            uint32_t bits = __ballot_sync(0xffffffffu, s);
            if (s) v = 0.f;
            if (lane == 0)
                outp[((t * BB + b) * NN + n) * NWD + wrp] = bits;
        }
    }
}

// ---------------------------------------------------------------------------
// K3: kv = sum_n (k AND v)  (exact integer), then LIF v_th=0.5 -> g_kvb
// grid (B), block 384 (thread = d)
// ---------------------------------------------------------------------------
__global__ void kv_kernel()
{
    int b = blockIdx.x;
    int d = threadIdx.x, lane = d & 31, wrp = d >> 5;
    __shared__ uint32_t ks[NN * NWD];
    __shared__ uint32_t vs[NN * NWD];
    float cnt[TT];
    for (int t = 0; t < TT; t++) {
        for (int i = d; i < NN * NWD; i += CC) {
            ks[i] = g_sk[(t * BB + b) * NN * NWD + i];
            vs[i] = g_sv[(t * BB + b) * NN * NWD + i];
        }
        __syncthreads();
        int s = 0;
        for (int n = 0; n < NN; n++)
            s += (int)(((ks[n * NWD + wrp] & vs[n * NWD + wrp]) >> lane) & 1u);
        cnt[t] = (float)s;
        __syncthreads();
    }
    float v = 0.f;
#pragma unroll
    for (int t = 0; t < TT; t++) {
        v += (cnt[t] - v) * 0.5f;
        int s = (v - 0.5f) >= 0.f;
        uint32_t bits = __ballot_sync(0xffffffffu, s);
        if (s) v = 0.f;
        if (lane == 0)
            g_kvb[(t * BB + b) * NWD + wrp] = bits;
    }
}

// ---------------------------------------------------------------------------
// K4: proj: sparse conv1x1 over y = (q AND kv) + bias + BN + identity -> out1
// grid (N/32, B, T), block 384.  Results staged in padded smem tile so the
// global writes (and identity reads) are coalesced along n.
// dynamic smem: 32*385*4 bytes
// ---------------------------------------------------------------------------
__global__ void proj_kernel(const float* __restrict__ x,
    const float* __restrict__ pb,  const float* __restrict__ pg, const float* __restrict__ pbt,
    const float* __restrict__ pm,  const float* __restrict__ pv, float* __restrict__ out1)
{
    extern __shared__ float tile[];            // [32][385]
    __shared__ float s_scale[CC], s_shift[CC];
    __shared__ uint32_t kvw[NWD];
    int t = blockIdx.z, b = blockIdx.y, n0 = blockIdx.x << 5;
    int d = threadIdx.x, lane = d & 31, wrp = d >> 5;
    float sc = pg[d] * rsqrtf(pv[d] + EPSB);
    s_scale[d] = sc;
    s_shift[d] = (pb[d] - pm[d]) * sc + pbt[d];
    if (d < NWD) kvw[d] = g_kvb[(t * BB + b) * NWD + d];
    __syncthreads();

    const float* wT = g_wT[3];
    for (int nl = 0; nl < 32; nl++) {
        int n = n0 + nl;
        const uint32_t* qw = &g_sq[((t * BB + b) * NN + n) * NWD];
        float a = 0.f;
#pragma unroll
        for (int w = 0; w < NWD; w++) {
            uint32_t m = qw[w] & kvw[w];
            while (m) {
                int c = (w << 5) + (__ffs(m) - 1);
                m &= m - 1;
                a += wT[c * CC + d];
            }
        }
        tile[nl * 385 + d] = a;
    }
    __syncthreads();
    // coalesced write phase: warp wrp writes row dd, lanes = consecutive n
    for (int i = 0; i < 32; i++) {
        int dd = i * NWD + wrp;
        int idx = ((t * BB + b) * CC + dd) * NN + n0 + lane;
        out1[idx] = tile[lane * 385 + dd] * s_scale[dd] + s_shift[dd] + x[idx];
    }
}

// ---------------------------------------------------------------------------
// K5: second output: v spikes reshaped to (T,B,h,N,Ch) as float
// ---------------------------------------------------------------------------
__global__ void vout_kernel(float* __restrict__ out2)
{
    int idx = blockIdx.x * 256 + threadIdx.x;      // grid sized exactly
    int ch = idx % 48;
    int r = idx / 48;
    int n = r % NN;  r /= NN;
    int h = r & 7;   r >>= 3;                      // r = t*BB + b
    int dd = h * 48 + ch;
    uint32_t wv = g_sv[(r * NN + n) * NWD + (dd >> 5)];
    out2[idx] = (float)((wv >> (dd & 31)) & 1u);
}

// ---------------------------------------------------------------------------
extern "C" void kernel_launch(void* const* d_in, const int* in_sizes, int n_in,
                              void* d_out, int out_size)
{
    const float* x    = (const float*)d_in[0];
    const float* q_w  = (const float*)d_in[1];
    const float* q_g  = (const float*)d_in[2];
    const float* q_b  = (const float*)d_in[3];
    const float* q_m  = (const float*)d_in[4];
    const float* q_v  = (const float*)d_in[5];
    const float* k_w  = (const float*)d_in[6];
    const float* k_g  = (const float*)d_in[7];
    const float* k_b  = (const float*)d_in[8];
    const float* k_m  = (const float*)d_in[9];
    const float* k_v  = (const float*)d_in[10];
    const float* v_w  = (const float*)d_in[11];
    const float* v_g  = (const float*)d_in[12];
    const float* v_b  = (const float*)d_in[13];
    const float* v_m  = (const float*)d_in[14];
    const float* v_v  = (const float*)d_in[15];
    const float* p_w  = (const float*)d_in[16];
    const float* p_b  = (const float*)d_in[17];
    const float* p_g  = (const float*)d_in[18];
    const float* p_bt = (const float*)d_in[19];
    const float* p_m  = (const float*)d_in[20];
    const float* p_v  = (const float*)d_in[21];
    float* out = (float*)d_out;

    cudaFuncSetAttribute(proj_kernel, cudaFuncAttributeMaxDynamicSharedMemorySize, 32 * 385 * 4);

    transpose_kernel<<<dim3(12, 12, 4), dim3(32, 32)>>>(q_w, k_w, v_w, p_w);
    lif_x_kernel<<<dim3(12, 8, 32), 1024>>>(x);
    qkv_kernel<<<dim3(256, 32), 384>>>(q_g, q_b, q_m, q_v,
                                       k_g, k_b, k_m, k_v,
                                       v_g, v_b, v_m, v_v);
    kv_kernel<<<32, 384>>>();
    proj_kernel<<<dim3(8, 32, 4), 384, 32 * 385 * 4>>>(x, p_b, p_g, p_bt, p_m, p_v, out);
    vout_kernel<<<OUT1_ELEMS / 256, 256>>>(out + OUT1_ELEMS);
}

// round 9
// speedup vs baseline: 3.0774x; 3.0774x over previous
#include <cuda_runtime.h>
#include <stdint.h>

// Problem constants (fixed shapes)
#define TT   4
#define BB   32
#define CC   384
#define NN   256          // H*W
#define NWD  12           // 384 bits / 32 = words per channel mask
#define EPSB 1e-5f
#define OUT1_ELEMS (TT*BB*CC*NN)   // 12,582,912

// Scratch (device globals; no allocation allowed)
__device__ uint32_t g_xs [TT*BB*NN*NWD];   // shortcut-LIF spikes, bits over c
__device__ uint32_t g_sq [TT*BB*NN*NWD];   // q spikes
__device__ uint32_t g_sk [TT*BB*NN*NWD];   // k spikes
__device__ uint32_t g_sv [TT*BB*NN*NWD];   // v spikes
__device__ int      g_cnt[TT*BB*CC];       // per (t,b,d) popcount of k&v over n
__device__ uint32_t g_kvb[TT*BB*NWD];      // kv-LIF spikes, bits over d
__device__ float    g_wT [4][CC*CC];       // transposed weights: wT[c*C + d]

// ---------------------------------------------------------------------------
// K0: transpose the 4 weight matrices (w[d][c] -> wT[c][d])
// ---------------------------------------------------------------------------
__global__ void transpose_kernel(const float* __restrict__ wq, const float* __restrict__ wk,
                                 const float* __restrict__ wv, const float* __restrict__ wp)
{
    __shared__ float tile[32][33];
    const float* src = (blockIdx.z == 0) ? wq : (blockIdx.z == 1) ? wk
                     : (blockIdx.z == 2) ? wv : wp;
    int d0 = blockIdx.x * 32, c0 = blockIdx.y * 32;
    tile[threadIdx.y][threadIdx.x] = src[(d0 + threadIdx.y) * CC + (c0 + threadIdx.x)];
    __syncthreads();
    g_wT[blockIdx.z][(c0 + threadIdx.y) * CC + (d0 + threadIdx.x)] = tile[threadIdx.x][threadIdx.y];
}

// ---------------------------------------------------------------------------
// K1: shortcut LIF on x -> bitpacked spikes g_xs
// grid (C/32, N/32, B), block 1024
// ---------------------------------------------------------------------------
__global__ void lif_x_kernel(const float* __restrict__ x)
{
    __shared__ float xt[TT][32][33];
    int b = blockIdx.z, c0 = blockIdx.x << 5, n0 = blockIdx.y << 5;
    int tid = threadIdx.x;
    int cl = tid >> 5, nl = tid & 31;
#pragma unroll
    for (int t = 0; t < TT; t++)
        xt[t][cl][nl] = x[((t * BB + b) * CC + c0 + cl) * NN + n0 + nl];
    __syncthreads();
    int lane = tid & 31;   // c within word
    int wrp  = tid >> 5;   // n within tile
    float v = 0.f;
#pragma unroll
    for (int t = 0; t < TT; t++) {
        float xv = xt[t][lane][wrp];
        v += (xv - v) * 0.5f;                 // TAU=2, exact halving
        int s = (v - 1.0f) >= 0.f;
        uint32_t bits = __ballot_sync(0xffffffffu, s);
        if (s) v = 0.f;
        if (lane == 0)
            g_xs[((t * BB + b) * NN + n0 + wrp) * NWD + (c0 >> 5)] = bits;
    }
}

// ---------------------------------------------------------------------------
// K2: fused q/k/v sparse conv1x1 + BN + LIF -> spike bits
// grid (N, B), block 384 (thread = output channel d).
// Cooperative decode: threads 0..3 build per-t active-channel lists (shared
// across all 3 branches); all threads then run an indexed unrolled gather.
// ---------------------------------------------------------------------------
__global__ void qkv_kernel(
    const float* __restrict__ qg, const float* __restrict__ qb, const float* __restrict__ qm, const float* __restrict__ qvv,
    const float* __restrict__ kg, const float* __restrict__ kb, const float* __restrict__ km, const float* __restrict__ kvv,
    const float* __restrict__ vg, const float* __restrict__ vb, const float* __restrict__ vm, const float* __restrict__ vvv)
{
    int n = blockIdx.x, b = blockIdx.y;
    int d = threadIdx.x, lane = d & 31, wrp = d >> 5;
    __shared__ uint16_t slist[TT][CC];
    __shared__ int scnt[TT];

    if (d < TT) {
        int t = d;
        const uint32_t* mp = &g_xs[((t * BB + b) * NN + n) * NWD];
        uint32_t mw[NWD];
#pragma unroll
        for (int w = 0; w < NWD; w++) mw[w] = mp[w];
        int c0 = 0;
#pragma unroll
        for (int w = 0; w < NWD; w++) {
            uint32_t m = mw[w];
            while (m) {
                slist[t][c0++] = (uint16_t)((w << 5) + (__ffs(m) - 1));
                m &= m - 1;
            }
        }
        scnt[t] = c0;
    }
    __syncthreads();

    for (int p = 0; p < 3; p++) {
        const float* wT = g_wT[p];
        float acc[TT];
#pragma unroll
        for (int t = 0; t < TT; t++) {
            int cnt = scnt[t];
            const uint16_t* L = slist[t];
            float a0 = 0.f, a1 = 0.f, a2 = 0.f, a3 = 0.f;
            int i = 0;
            for (; i + 3 < cnt; i += 4) {
                a0 += wT[(int)L[i]     * CC + d];
                a1 += wT[(int)L[i + 1] * CC + d];
                a2 += wT[(int)L[i + 2] * CC + d];
                a3 += wT[(int)L[i + 3] * CC + d];
            }
            for (; i < cnt; i++) a0 += wT[(int)L[i] * CC + d];
            acc[t] = (a0 + a1) + (a2 + a3);
        }
        const float *gm, *bt, *mn, *vr;
        uint32_t* outp;
        if (p == 0)      { gm = qg; bt = qb; mn = qm; vr = qvv; outp = g_sq; }
        else if (p == 1) { gm = kg; bt = kb; mn = km; vr = kvv; outp = g_sk; }
        else             { gm = vg; bt = vb; mn = vm; vr = vvv; outp = g_sv; }
        float scale = gm[d] * rsqrtf(vr[d] + EPSB);
        float mean = mn[d], beta = bt[d];
        float v = 0.f;
#pragma unroll
        for (int t = 0; t < TT; t++) {
            float u = (acc[t] - mean) * scale + beta;
            v += (u - v) * 0.5f;
            int s = (v - 1.0f) >= 0.f;
            uint32_t bits = __ballot_sync(0xffffffffu, s);
            if (s) v = 0.f;
            if (lane == 0)
                outp[((t * BB + b) * NN + n) * NWD + wrp] = bits;
        }
    }
}

// ---------------------------------------------------------------------------
// K3a: per-(t,b,d) popcount of (k AND v) over n.  grid (B, T), block 384.
// AND fused at load into padded word-major smem (broadcast reads, no conflicts)
// ---------------------------------------------------------------------------
__global__ void kvcount_kernel()
{
    __shared__ uint32_t sa[NWD * 257];
    int b = blockIdx.x, t = blockIdx.y;
    int d = threadIdx.x, lane = d & 31, wrp = d >> 5;
    const uint32_t* gk = &g_sk[(t * BB + b) * NN * NWD];
    const uint32_t* gv = &g_sv[(t * BB + b) * NN * NWD];
    for (int i = d; i < NN * NWD; i += CC) {
        int n = i / NWD, w = i % NWD;
        sa[w * 257 + n] = gk[i] & gv[i];
    }
    __syncthreads();
    int c = 0;
    const uint32_t* row = &sa[wrp * 257];
#pragma unroll 8
    for (int n = 0; n < NN; n++)
        c += (int)((row[n] >> lane) & 1u);
    g_cnt[(t * BB + b) * CC + d] = c;
}

// K3b: LIF (v_th=0.5) over the 4 counts -> kv spike bits.  grid (B), block 384
__global__ void kvlif_kernel()
{
    int b = blockIdx.x;
    int d = threadIdx.x, lane = d & 31, wrp = d >> 5;
    float v = 0.f;
#pragma unroll
    for (int t = 0; t < TT; t++) {
        float cnt = (float)g_cnt[(t * BB + b) * CC + d];
        v += (cnt - v) * 0.5f;
        int s = (v - 0.5f) >= 0.f;
        uint32_t bits = __ballot_sync(0xffffffffu, s);
        if (s) v = 0.f;
        if (lane == 0)
            g_kvb[(t * BB + b) * NWD + wrp] = bits;
    }
}

// ---------------------------------------------------------------------------
// K4: proj: sparse conv1x1 over y = (q AND kv) + bias + BN + identity -> out1
// grid (N/32, B, T), block 384.  Cooperative per-column list decode; smem
// tile transpose for coalesced output writes.  dynamic smem: 32*385*4 B
// ---------------------------------------------------------------------------
__global__ void proj_kernel(const float* __restrict__ x,
    const float* __restrict__ pb,  const float* __restrict__ pg, const float* __restrict__ pbt,
    const float* __restrict__ pm,  const float* __restrict__ pv, float* __restrict__ out1)
{
    extern __shared__ float tile[];            // [32][385]
    __shared__ float s_scale[CC], s_shift[CC];
    __shared__ uint32_t kvw[NWD];
    __shared__ uint32_t sqw[32 * NWD];
    __shared__ uint16_t slist[32][CC];
    __shared__ int scnt[32];
    int t = blockIdx.z, b = blockIdx.y, n0 = blockIdx.x << 5;
    int d = threadIdx.x, lane = d & 31, wrp = d >> 5;
    float sc = pg[d] * rsqrtf(pv[d] + EPSB);
    s_scale[d] = sc;
    s_shift[d] = (pb[d] - pm[d]) * sc + pbt[d];
    if (d < NWD) kvw[d] = g_kvb[(t * BB + b) * NWD + d];
    sqw[d] = g_sq[((t * BB + b) * NN + n0) * NWD + d];   // 32 cols x 12 words, coalesced
    __syncthreads();

    if (d < 32) {  // decode q AND kv for column n0+d
        int c0 = 0;
#pragma unroll
        for (int w = 0; w < NWD; w++) {
            uint32_t m = sqw[d * NWD + w] & kvw[w];
            while (m) {
                slist[d][c0++] = (uint16_t)((w << 5) + (__ffs(m) - 1));
                m &= m - 1;
            }
        }
        scnt[d] = c0;
    }
    __syncthreads();

    const float* wT = g_wT[3];
    for (int nl = 0; nl < 32; nl++) {
        int cnt = scnt[nl];
        const uint16_t* L = slist[nl];
        float a0 = 0.f, a1 = 0.f, a2 = 0.f, a3 = 0.f;
        int i = 0;
        for (; i + 3 < cnt; i += 4) {
            a0 += wT[(int)L[i]     * CC + d];
            a1 += wT[(int)L[i + 1] * CC + d];
            a2 += wT[(int)L[i + 2] * CC + d];
            a3 += wT[(int)L[i + 3] * CC + d];
        }
        for (; i < cnt; i++) a0 += wT[(int)L[i] * CC + d];
        tile[nl * 385 + d] = (a0 + a1) + (a2 + a3);
    }
    __syncthreads();
    // coalesced write phase: warp wrp writes row dd, lanes = consecutive n
    for (int i = 0; i < 32; i++) {
        int dd = i * NWD + wrp;
        int idx = ((t * BB + b) * CC + dd) * NN + n0 + lane;
        out1[idx] = tile[lane * 385 + dd] * s_scale[dd] + s_shift[dd] + x[idx];
    }
}

// ---------------------------------------------------------------------------
// K5: second output: v spikes reshaped to (T,B,h,N,Ch) as float.
// Each thread emits 4 consecutive ch values from one spike-word read.
// ---------------------------------------------------------------------------
__global__ void vout_kernel(float* __restrict__ out2)
{
    int q = blockIdx.x * 256 + threadIdx.x;        // q indexes groups of 4 ch
    int ch4 = (q % 12) * 4;                        // 48 ch / 4 = 12 groups
    int r = q / 12;
    int n = r % NN;  r /= NN;
    int h = r & 7;   r >>= 3;                      // r = t*BB + b
    int dd = h * 48 + ch4;
    uint32_t wv = g_sv[(r * NN + n) * NWD + (dd >> 5)];
    int sh = dd & 31;
    float4 o;
    o.x = (float)((wv >> (sh + 0)) & 1u);
    o.y = (float)((wv >> (sh + 1)) & 1u);
    o.z = (float)((wv >> (sh + 2)) & 1u);
    o.w = (float)((wv >> (sh + 3)) & 1u);
    *reinterpret_cast<float4*>(out2 + q * 4) = o;
}

// ---------------------------------------------------------------------------
extern "C" void kernel_launch(void* const* d_in, const int* in_sizes, int n_in,
                              void* d_out, int out_size)
{
    const float* x    = (const float*)d_in[0];
    const float* q_w  = (const float*)d_in[1];
    const float* q_g  = (const float*)d_in[2];
    const float* q_b  = (const float*)d_in[3];
    const float* q_m  = (const float*)d_in[4];
    const float* q_v  = (const float*)d_in[5];
    const float* k_w  = (const float*)d_in[6];
    const float* k_g  = (const float*)d_in[7];
    const float* k_b  = (const float*)d_in[8];
    const float* k_m  = (const float*)d_in[9];
    const float* k_v  = (const float*)d_in[10];
    const float* v_w  = (const float*)d_in[11];
    const float* v_g  = (const float*)d_in[12];
    const float* v_b  = (const float*)d_in[13];
    const float* v_m  = (const float*)d_in[14];
    const float* v_v  = (const float*)d_in[15];
    const float* p_w  = (const float*)d_in[16];
    const float* p_b  = (const float*)d_in[17];
    const float* p_g  = (const float*)d_in[18];
    const float* p_bt = (const float*)d_in[19];
    const float* p_m  = (const float*)d_in[20];
    const float* p_v  = (const float*)d_in[21];
    float* out = (float*)d_out;

    cudaFuncSetAttribute(proj_kernel, cudaFuncAttributeMaxDynamicSharedMemorySize, 32 * 385 * 4);

    transpose_kernel<<<dim3(12, 12, 4), dim3(32, 32)>>>(q_w, k_w, v_w, p_w);
    lif_x_kernel<<<dim3(12, 8, 32), 1024>>>(x);
    qkv_kernel<<<dim3(256, 32), 384>>>(q_g, q_b, q_m, q_v,
                                       k_g, k_b, k_m, k_v,
                                       v_g, v_b, v_m, v_v);
    kvcount_kernel<<<dim3(32, 4), 384>>>();
    kvlif_kernel<<<32, 384>>>();
    proj_kernel<<<dim3(8, 32, 4), 384, 32 * 385 * 4>>>(x, p_b, p_g, p_bt, p_m, p_v, out);
    vout_kernel<<<OUT1_ELEMS / 4 / 256, 256>>>(out + OUT1_ELEMS);
}

// round 10
// speedup vs baseline: 3.1213x; 1.0143x over previous
#include <cuda_runtime.h>
#include <cuda_fp16.h>
#include <stdint.h>

// Problem constants (fixed shapes)
#define TT   4
#define BB   32
#define CC   384
#define NN   256          // H*W
#define NWD  12           // 384 bits / 32 = words per channel mask
#define EPSB 1e-5f
#define OUT1_ELEMS (TT*BB*CC*NN)   // 12,582,912
#define ROWB (CC*2)                // bytes per fp16 weight row (768)

// Scratch (device globals; no allocation allowed)
__device__ uint32_t g_xs [TT*BB*NN*NWD];   // shortcut-LIF spikes, bits over c
__device__ uint32_t g_sq [TT*BB*NN*NWD];   // q spikes
__device__ uint32_t g_sk [TT*BB*NN*NWD];   // k spikes
__device__ uint32_t g_sv [TT*BB*NN*NWD];   // v spikes
__device__ int      g_cnt[4][TT*BB*CC];    // partial popcounts of k&v over n-chunks
__device__ uint32_t g_kvb[TT*BB*NWD];      // kv-LIF spikes, bits over d
__device__ __half   g_wT [4][CC*CC];       // transposed fp16 weights: wT[c*C + d]

// ---------------------------------------------------------------------------
// K0: transpose the 4 weight matrices (w[d][c] -> wT[c][d]) and cast to fp16
// ---------------------------------------------------------------------------
__global__ void transpose_kernel(const float* __restrict__ wq, const float* __restrict__ wk,
                                 const float* __restrict__ wv, const float* __restrict__ wp)
{
    __shared__ float tile[32][33];
    const float* src = (blockIdx.z == 0) ? wq : (blockIdx.z == 1) ? wk
                     : (blockIdx.z == 2) ? wv : wp;
    int d0 = blockIdx.x * 32, c0 = blockIdx.y * 32;
    tile[threadIdx.y][threadIdx.x] = src[(d0 + threadIdx.y) * CC + (c0 + threadIdx.x)];
    __syncthreads();
    g_wT[blockIdx.z][(c0 + threadIdx.y) * CC + (d0 + threadIdx.x)] =
        __float2half_rn(tile[threadIdx.x][threadIdx.y]);
}

// ---------------------------------------------------------------------------
// K1: shortcut LIF on x -> bitpacked spikes g_xs
// grid (C/32, N/32, B), block 1024
// ---------------------------------------------------------------------------
__global__ void lif_x_kernel(const float* __restrict__ x)
{
    __shared__ float xt[TT][32][33];
    int b = blockIdx.z, c0 = blockIdx.x << 5, n0 = blockIdx.y << 5;
    int tid = threadIdx.x;
    int cl = tid >> 5, nl = tid & 31;
#pragma unroll
    for (int t = 0; t < TT; t++)
        xt[t][cl][nl] = x[((t * BB + b) * CC + c0 + cl) * NN + n0 + nl];
    __syncthreads();
    int lane = tid & 31;   // c within word
    int wrp  = tid >> 5;   // n within tile
    float v = 0.f;
#pragma unroll
    for (int t = 0; t < TT; t++) {
        float xv = xt[t][lane][wrp];
        v += (xv - v) * 0.5f;                 // TAU=2, exact halving
        int s = (v - 1.0f) >= 0.f;
        uint32_t bits = __ballot_sync(0xffffffffu, s);
        if (s) v = 0.f;
        if (lane == 0)
            g_xs[((t * BB + b) * NN + n0 + wrp) * NWD + (c0 >> 5)] = bits;
    }
}

// ---------------------------------------------------------------------------
// K2: fused q/k/v sparse conv1x1 + BN + LIF -> spike bits
// grid (N, B), block 384 (thread = output channel d).
// Lists hold pre-scaled byte offsets (c * 768) into the fp16 weight matrix.
// ---------------------------------------------------------------------------
__global__ void qkv_kernel(
    const float* __restrict__ qg, const float* __restrict__ qb, const float* __restrict__ qm, const float* __restrict__ qvv,
    const float* __restrict__ kg, const float* __restrict__ kb, const float* __restrict__ km, const float* __restrict__ kvv,
    const float* __restrict__ vg, const float* __restrict__ vb, const float* __restrict__ vm, const float* __restrict__ vvv)
{
    int n = blockIdx.x, b = blockIdx.y;
    int d = threadIdx.x, lane = d & 31, wrp = d >> 5;
    __shared__ uint32_t slist[TT][CC];
    __shared__ int scnt[TT];

    if (d < TT) {
        int t = d;
        const uint32_t* mp = &g_xs[((t * BB + b) * NN + n) * NWD];
        uint32_t mw[NWD];
#pragma unroll
        for (int w = 0; w < NWD; w++) mw[w] = mp[w];
        int c0 = 0;
#pragma unroll
        for (int w = 0; w < NWD; w++) {
            uint32_t m = mw[w];
            while (m) {
                slist[t][c0++] = (uint32_t)(((w << 5) + (__ffs(m) - 1)) * ROWB);
                m &= m - 1;
            }
        }
        scnt[t] = c0;
    }
    __syncthreads();

    int dofs = d << 1;   // byte offset of this thread's fp16 element within a row
    for (int p = 0; p < 3; p++) {
        const char* wT = (const char*)g_wT[p];
        float acc[TT];
#pragma unroll
        for (int t = 0; t < TT; t++) {
            int cnt = scnt[t];
            const uint32_t* L = slist[t];
            float a0 = 0.f, a1 = 0.f, a2 = 0.f, a3 = 0.f;
            int i = 0;
            for (; i + 3 < cnt; i += 4) {
                a0 += __half2float(*(const __half*)(wT + L[i]     + dofs));
                a1 += __half2float(*(const __half*)(wT + L[i + 1] + dofs));
                a2 += __half2float(*(const __half*)(wT + L[i + 2] + dofs));
                a3 += __half2float(*(const __half*)(wT + L[i + 3] + dofs));
            }
            for (; i < cnt; i++) a0 += __half2float(*(const __half*)(wT + L[i] + dofs));
            acc[t] = (a0 + a1) + (a2 + a3);
        }
        const float *gm, *bt, *mn, *vr;
        uint32_t* outp;
        if (p == 0)      { gm = qg; bt = qb; mn = qm; vr = qvv; outp = g_sq; }
        else if (p == 1) { gm = kg; bt = kb; mn = km; vr = kvv; outp = g_sk; }
        else             { gm = vg; bt = vb; mn = vm; vr = vvv; outp = g_sv; }
        float scale = gm[d] * rsqrtf(vr[d] + EPSB);
        float mean = mn[d], beta = bt[d];
        float v = 0.f;
#pragma unroll
        for (int t = 0; t < TT; t++) {
            float u = (acc[t] - mean) * scale + beta;
            v += (u - v) * 0.5f;
            int s = (v - 1.0f) >= 0.f;
            uint32_t bits = __ballot_sync(0xffffffffu, s);
            if (s) v = 0.f;
            if (lane == 0)
                outp[((t * BB + b) * NN + n) * NWD + wrp] = bits;
        }
    }
}

// ---------------------------------------------------------------------------
// K3a: partial popcount of (k AND v) over a 64-n chunk.  grid (B, T, 4).
// ---------------------------------------------------------------------------
__global__ void kvcount_kernel()
{
    __shared__ uint32_t sa[NWD * 65];
    int b = blockIdx.x, t = blockIdx.y, z = blockIdx.z;
    int d = threadIdx.x, lane = d & 31, wrp = d >> 5;
    const uint32_t* gk = &g_sk[((t * BB + b) * NN + z * 64) * NWD];
    const uint32_t* gv = &g_sv[((t * BB + b) * NN + z * 64) * NWD];
    for (int i = d; i < 64 * NWD; i += CC) {
        int n = i / NWD, w = i % NWD;
        sa[w * 65 + n] = gk[i] & gv[i];
    }
    __syncthreads();
    int c = 0;
    const uint32_t* row = &sa[wrp * 65];
#pragma unroll 8
    for (int n = 0; n < 64; n++)
        c += (int)((row[n] >> lane) & 1u);
    g_cnt[z][(t * BB + b) * CC + d] = c;
}

// K3b: LIF (v_th=0.5) over summed counts -> kv spike bits.  grid (B), block 384
__global__ void kvlif_kernel()
{
    int b = blockIdx.x;
    int d = threadIdx.x, lane = d & 31, wrp = d >> 5;
    float v = 0.f;
#pragma unroll
    for (int t = 0; t < TT; t++) {
        int idx = (t * BB + b) * CC + d;
        float cnt = (float)(g_cnt[0][idx] + g_cnt[1][idx] + g_cnt[2][idx] + g_cnt[3][idx]);
        v += (cnt - v) * 0.5f;
        int s = (v - 0.5f) >= 0.f;
        uint32_t bits = __ballot_sync(0xffffffffu, s);
        if (s) v = 0.f;
        if (lane == 0)
            g_kvb[(t * BB + b) * NWD + wrp] = bits;
    }
}

// ---------------------------------------------------------------------------
// K4: proj: sparse conv1x1 over y = (q AND kv) + bias + BN + identity -> out1
// grid (N/32, B, T), block 384.  fp16 weights, byte-offset lists, smem-tiled
// transpose for coalesced writes.  dynamic smem: 32*385*4 B
// ---------------------------------------------------------------------------
__global__ void proj_kernel(const float* __restrict__ x,
    const float* __restrict__ pb,  const float* __restrict__ pg, const float* __restrict__ pbt,
    const float* __restrict__ pm,  const float* __restrict__ pv, float* __restrict__ out1)
{
    extern __shared__ float tile[];            // [32][385]
    __shared__ float s_scale[CC], s_shift[CC];
    __shared__ uint32_t kvw[NWD];
    __shared__ uint32_t sqw[32 * NWD];
    __shared__ uint32_t slist[32][CC];
    __shared__ int scnt[32];
    int t = blockIdx.z, b = blockIdx.y, n0 = blockIdx.x << 5;
    int d = threadIdx.x, lane = d & 31, wrp = d >> 5;
    float sc = pg[d] * rsqrtf(pv[d] + EPSB);
    s_scale[d] = sc;
    s_shift[d] = (pb[d] - pm[d]) * sc + pbt[d];
    if (d < NWD) kvw[d] = g_kvb[(t * BB + b) * NWD + d];
    sqw[d] = g_sq[((t * BB + b) * NN + n0) * NWD + d];   // 32 cols x 12 words, coalesced
    __syncthreads();

    if (d < 32) {  // decode q AND kv for column n0+d
        int c0 = 0;
#pragma unroll
        for (int w = 0; w < NWD; w++) {
            uint32_t m = sqw[d * NWD + w] & kvw[w];
            while (m) {
                slist[d][c0++] = (uint32_t)(((w << 5) + (__ffs(m) - 1)) * ROWB);
                m &= m - 1;
            }
        }
        scnt[d] = c0;
    }
    __syncthreads();

    const char* wT = (const char*)g_wT[3];
    int dofs = d << 1;
    for (int nl = 0; nl < 32; nl++) {
        int cnt = scnt[nl];
        const uint32_t* L = slist[nl];
        float a0 = 0.f, a1 = 0.f, a2 = 0.f, a3 = 0.f;
        int i = 0;
        for (; i + 3 < cnt; i += 4) {
            a0 += __half2float(*(const __half*)(wT + L[i]     + dofs));
            a1 += __half2float(*(const __half*)(wT + L[i + 1] + dofs));
            a2 += __half2float(*(const __half*)(wT + L[i + 2] + dofs));
            a3 += __half2float(*(const __half*)(wT + L[i + 3] + dofs));
        }
        for (; i < cnt; i++) a0 += __half2float(*(const __half*)(wT + L[i] + dofs));
        tile[nl * 385 + d] = (a0 + a1) + (a2 + a3);
    }
    __syncthreads();
    // coalesced write phase: warp wrp writes row dd, lanes = consecutive n
    for (int i = 0; i < 32; i++) {
        int dd = i * NWD + wrp;
        int idx = ((t * BB + b) * CC + dd) * NN + n0 + lane;
        out1[idx] = tile[lane * 385 + dd] * s_scale[dd] + s_shift[dd] + x[idx];
    }
}

// ---------------------------------------------------------------------------
// K5: second output: v spikes reshaped to (T,B,h,N,Ch) as float.
// Each thread emits 4 consecutive ch values from one spike-word read.
// ---------------------------------------------------------------------------
__global__ void vout_kernel(float* __restrict__ out2)
{
    int q = blockIdx.x * 256 + threadIdx.x;        // q indexes groups of 4 ch
    int ch4 = (q % 12) * 4;                        // 48 ch / 4 = 12 groups
    int r = q / 12;
    int n = r % NN;  r /= NN;
    int h = r & 7;   r >>= 3;                      // r = t*BB + b
    int dd = h * 48 + ch4;
    uint32_t wv = g_sv[(r * NN + n) * NWD + (dd >> 5)];
    int sh = dd & 31;
    float4 o;
    o.x = (float)((wv >> (sh + 0)) & 1u);
    o.y = (float)((wv >> (sh + 1)) & 1u);
    o.z = (float)((wv >> (sh + 2)) & 1u);
    o.w = (float)((wv >> (sh + 3)) & 1u);
    *reinterpret_cast<float4*>(out2 + q * 4) = o;
}

// ---------------------------------------------------------------------------
extern "C" void kernel_launch(void* const* d_in, const int* in_sizes, int n_in,
                              void* d_out, int out_size)
{
    const float* x    = (const float*)d_in[0];
    const float* q_w  = (const float*)d_in[1];
    const float* q_g  = (const float*)d_in[2];
    const float* q_b  = (const float*)d_in[3];
    const float* q_m  = (const float*)d_in[4];
    const float* q_v  = (const float*)d_in[5];
    const float* k_w  = (const float*)d_in[6];
    const float* k_g  = (const float*)d_in[7];
    const float* k_b  = (const float*)d_in[8];
    const float* k_m  = (const float*)d_in[9];
    const float* k_v  = (const float*)d_in[10];
    const float* v_w  = (const float*)d_in[11];
    const float* v_g  = (const float*)d_in[12];
    const float* v_b  = (const float*)d_in[13];
    const float* v_m  = (const float*)d_in[14];
    const float* v_v  = (const float*)d_in[15];
    const float* p_w  = (const float*)d_in[16];
    const float* p_b  = (const float*)d_in[17];
    const float* p_g  = (const float*)d_in[18];
    const float* p_bt = (const float*)d_in[19];
    const float* p_m  = (const float*)d_in[20];
    const float* p_v  = (const float*)d_in[21];
    float* out = (float*)d_out;

    cudaFuncSetAttribute(proj_kernel, cudaFuncAttributeMaxDynamicSharedMemorySize, 32 * 385 * 4);

    transpose_kernel<<<dim3(12, 12, 4), dim3(32, 32)>>>(q_w, k_w, v_w, p_w);
    lif_x_kernel<<<dim3(12, 8, 32), 1024>>>(x);
    qkv_kernel<<<dim3(256, 32), 384>>>(q_g, q_b, q_m, q_v,
                                       k_g, k_b, k_m, k_v,
                                       v_g, v_b, v_m, v_v);
    kvcount_kernel<<<dim3(32, 4, 4), 384>>>();
    kvlif_kernel<<<32, 384>>>();
    proj_kernel<<<dim3(8, 32, 4), 384, 32 * 385 * 4>>>(x, p_b, p_g, p_bt, p_m, p_v, out);
    vout_kernel<<<OUT1_ELEMS / 4 / 256, 256>>>(out + OUT1_ELEMS);
}

// round 14
// speedup vs baseline: 4.0583x; 1.3002x over previous
#include <cuda_runtime.h>
#include <stdint.h>

// Problem constants (fixed shapes)
#define TT   4
#define BB   32
#define CC   384
#define NN   256          // H*W
#define NWD  12           // 384 bits / 32 = words per channel mask
#define EPSB 1e-5f
#define OUT1_ELEMS (TT*BB*CC*NN)   // 12,582,912
#define ROWB (CC*4)                // bytes per fp32 weight row (1536)

// Scratch (device globals; no allocation allowed)
__device__ uint32_t g_xs [TT*BB*NN*NWD];   // shortcut-LIF spikes, bits over c
__device__ uint32_t g_sq [TT*BB*NN*NWD];   // q spikes
__device__ uint32_t g_sk [TT*BB*NN*NWD];   // k spikes
__device__ uint32_t g_sv [TT*BB*NN*NWD];   // v spikes
__device__ int      g_cnt[8][TT*BB*CC];    // partial popcounts of k&v over n-chunks
__device__ uint32_t g_kvb[TT*BB*NWD];      // kv-LIF spikes, bits over d
__device__ float    g_wT [4][CC*CC];       // transposed fp32 weights: wT[c*C + d]

// ---------------------------------------------------------------------------
// K0: transpose the 4 weight matrices (w[d][c] -> wT[c][d])
// ---------------------------------------------------------------------------
__global__ void transpose_kernel(const float* __restrict__ wq, const float* __restrict__ wk,
                                 const float* __restrict__ wv, const float* __restrict__ wp)
{
    __shared__ float tile[32][33];
    const float* src = (blockIdx.z == 0) ? wq : (blockIdx.z == 1) ? wk
                     : (blockIdx.z == 2) ? wv : wp;
    int d0 = blockIdx.x * 32, c0 = blockIdx.y * 32;
    tile[threadIdx.y][threadIdx.x] = src[(d0 + threadIdx.y) * CC + (c0 + threadIdx.x)];
    __syncthreads();
    g_wT[blockIdx.z][(c0 + threadIdx.y) * CC + (d0 + threadIdx.x)] = tile[threadIdx.x][threadIdx.y];
}

// ---------------------------------------------------------------------------
// K1: shortcut LIF on x -> bitpacked spikes g_xs
// grid (C/32, N/32, B), block 1024
// ---------------------------------------------------------------------------
__global__ void lif_x_kernel(const float* __restrict__ x)
{
    __shared__ float xt[TT][32][33];
    int b = blockIdx.z, c0 = blockIdx.x << 5, n0 = blockIdx.y << 5;
    int tid = threadIdx.x;
    int cl = tid >> 5, nl = tid & 31;
#pragma unroll
    for (int t = 0; t < TT; t++)
        xt[t][cl][nl] = x[((t * BB + b) * CC + c0 + cl) * NN + n0 + nl];
    __syncthreads();
    int lane = tid & 31;   // c within word
    int wrp  = tid >> 5;   // n within tile
    float v = 0.f;
#pragma unroll
    for (int t = 0; t < TT; t++) {
        float xv = xt[t][lane][wrp];
        v += (xv - v) * 0.5f;                 // TAU=2, exact halving
        int s = (v - 1.0f) >= 0.f;
        uint32_t bits = __ballot_sync(0xffffffffu, s);
        if (s) v = 0.f;
        if (lane == 0)
            g_xs[((t * BB + b) * NN + n0 + wrp) * NWD + (c0 >> 5)] = bits;
    }
}

// ---------------------------------------------------------------------------
// K2: fused q/k/v sparse conv1x1 + BN + LIF -> spike bits (+ v spikes as fp32)
// grid (N, B), block 384 = 12 warps.  Warp w owns (p = w>>2, t = w&3); each
// lane owns 12 consecutive output channels loaded as 3x float4 per active row.
// Partial sums staged in smem; 384-thread LIF/ballot phase follows.
// ---------------------------------------------------------------------------
__global__ void qkv_kernel(
    const float* __restrict__ qg, const float* __restrict__ qb, const float* __restrict__ qm, const float* __restrict__ qvv,
    const float* __restrict__ kg, const float* __restrict__ kb, const float* __restrict__ km, const float* __restrict__ kvv,
    const float* __restrict__ vg, const float* __restrict__ vb, const float* __restrict__ vm, const float* __restrict__ vvv,
    float* __restrict__ out2)
{
    int n = blockIdx.x, b = blockIdx.y;
    int tid = threadIdx.x;
    int wid = tid >> 5, lane = tid & 31;
    __shared__ uint32_t slist[TT][CC];
    __shared__ int scnt[TT];
    __shared__ float sacc[3][TT][CC];

    if (tid < TT) {
        int t = tid;
        const uint32_t* mp = &g_xs[((t * BB + b) * NN + n) * NWD];
        uint32_t mw[NWD];
#pragma unroll
        for (int w = 0; w < NWD; w++) mw[w] = mp[w];
        int c0 = 0;
#pragma unroll
        for (int w = 0; w < NWD; w++) {
            uint32_t m = mw[w];
            while (m) {
                slist[t][c0++] = (uint32_t)(((w << 5) + (__ffs(m) - 1)) * ROWB);
                m &= m - 1;
            }
        }
        scnt[t] = c0;
    }
    __syncthreads();

    // --- gather phase: one warp per (branch, timestep) ---
    {
        int p = wid >> 2, t = wid & 3;
        const char* wTb = (const char*)g_wT[p];
        int lofs = lane * 48;                 // 12 fp32 channels per lane
        int cnt = scnt[t];
        const uint32_t* L = slist[t];
        float acc[12];
#pragma unroll
        for (int j = 0; j < 12; j++) acc[j] = 0.f;
        int i = 0;
        for (; i + 1 < cnt; i += 2) {
            const float4* r0 = (const float4*)(wTb + L[i]     + lofs);
            const float4* r1 = (const float4*)(wTb + L[i + 1] + lofs);
            float4 x0 = r0[0], x1 = r0[1], x2 = r0[2];
            float4 y0 = r1[0], y1 = r1[1], y2 = r1[2];
            acc[0] += x0.x; acc[1] += x0.y; acc[2]  += x0.z; acc[3]  += x0.w;
            acc[4] += x1.x; acc[5] += x1.y; acc[6]  += x1.z; acc[7]  += x1.w;
            acc[8] += x2.x; acc[9] += x2.y; acc[10] += x2.z; acc[11] += x2.w;
            acc[0] += y0.x; acc[1] += y0.y; acc[2]  += y0.z; acc[3]  += y0.w;
            acc[4] += y1.x; acc[5] += y1.y; acc[6]  += y1.z; acc[7]  += y1.w;
            acc[8] += y2.x; acc[9] += y2.y; acc[10] += y2.z; acc[11] += y2.w;
        }
        if (i < cnt) {
            const float4* r0 = (const float4*)(wTb + L[i] + lofs);
            float4 x0 = r0[0], x1 = r0[1], x2 = r0[2];
            acc[0] += x0.x; acc[1] += x0.y; acc[2]  += x0.z; acc[3]  += x0.w;
            acc[4] += x1.x; acc[5] += x1.y; acc[6]  += x1.z; acc[7]  += x1.w;
            acc[8] += x2.x; acc[9] += x2.y; acc[10] += x2.z; acc[11] += x2.w;
        }
        float* dst = &sacc[p][t][lane * 12];
#pragma unroll
        for (int j = 0; j < 12; j++) dst[j] = acc[j];
    }
    __syncthreads();

    // --- BN + LIF + ballot phase: thread = output channel d ---
    int d = tid, lane2 = d & 31, wrp = d >> 5;
    int h = d / 48, ch = d % 48;
    for (int p = 0; p < 3; p++) {
        const float *gm, *bt, *mn, *vr;
        uint32_t* outp;
        if (p == 0)      { gm = qg; bt = qb; mn = qm; vr = qvv; outp = g_sq; }
        else if (p == 1) { gm = kg; bt = kb; mn = km; vr = kvv; outp = g_sk; }
        else             { gm = vg; bt = vb; mn = vm; vr = vvv; outp = g_sv; }
        float scale = gm[d] * rsqrtf(vr[d] + EPSB);
        float mean = mn[d], beta = bt[d];
        float v = 0.f;
#pragma unroll
        for (int t = 0; t < TT; t++) {
            float u = (sacc[p][t][d] - mean) * scale + beta;
            v += (u - v) * 0.5f;
            int s = (v - 1.0f) >= 0.f;
            uint32_t bits = __ballot_sync(0xffffffffu, s);
            if (s) v = 0.f;
            if (lane2 == 0)
                outp[((t * BB + b) * NN + n) * NWD + wrp] = bits;
            if (p == 2)  // v spikes are output[1]: (T,B,h,N,Ch)
                out2[(((t * BB + b) * 8 + h) * NN + n) * 48 + ch] = (float)s;
        }
    }
}

// ---------------------------------------------------------------------------
// K3a: partial popcount of (k AND v) over a 32-n chunk.  grid (B, T, 8).
// ---------------------------------------------------------------------------
__global__ void kvcount_kernel()
{
    __shared__ uint32_t sa[NWD * 33];
    int b = blockIdx.x, t = blockIdx.y, z = blockIdx.z;
    int d = threadIdx.x, lane = d & 31, wrp = d >> 5;
    const uint32_t* gk = &g_sk[((t * BB + b) * NN + z * 32) * NWD];
    const uint32_t* gv = &g_sv[((t * BB + b) * NN + z * 32) * NWD];
    {   // 32*12 = 384 words: exactly one per thread
        int nn = d / NWD, w = d % NWD;
        sa[w * 33 + nn] = gk[d] & gv[d];
    }
    __syncthreads();
    int c = 0;
    const uint32_t* row = &sa[wrp * 33];
#pragma unroll
    for (int nn = 0; nn < 32; nn++)
        c += (int)((row[nn] >> lane) & 1u);
    g_cnt[z][(t * BB + b) * CC + d] = c;
}

// K3b: LIF (v_th=0.5) over summed counts -> kv spike bits.  grid (B), block 384
__global__ void kvlif_kernel()
{
    int b = blockIdx.x;
    int d = threadIdx.x, lane = d & 31, wrp = d >> 5;
    float v = 0.f;
#pragma unroll
    for (int t = 0; t < TT; t++) {
        int idx = (t * BB + b) * CC + d;
        int c = 0;
#pragma unroll
        for (int z = 0; z < 8; z++) c += g_cnt[z][idx];
        float cnt = (float)c;
        v += (cnt - v) * 0.5f;
        int s = (v - 0.5f) >= 0.f;
        uint32_t bits = __ballot_sync(0xffffffffu, s);
        if (s) v = 0.f;
        if (lane == 0)
            g_kvb[(t * BB + b) * NWD + wrp] = bits;
    }
}

// ---------------------------------------------------------------------------
// K4: proj: sparse conv1x1 over y = (q AND kv) + bias + BN + identity -> out1
// grid (N/32, B, T), block 384.  fp32 weights, byte-offset lists, smem-tiled
// transpose for coalesced writes.  dynamic smem: 32*385*4 B
// ---------------------------------------------------------------------------
__global__ void proj_kernel(const float* __restrict__ x,
    const float* __restrict__ pb,  const float* __restrict__ pg, const float* __restrict__ pbt,
    const float* __restrict__ pm,  const float* __restrict__ pv, float* __restrict__ out1)
{
    extern __shared__ float tile[];            // [32][385]
    __shared__ float s_scale[CC], s_shift[CC];
    __shared__ uint32_t kvw[NWD];
    __shared__ uint32_t sqw[32 * NWD];
    __shared__ uint32_t slist[32][CC];
    __shared__ int scnt[32];
    int t = blockIdx.z, b = blockIdx.y, n0 = blockIdx.x << 5;
    int d = threadIdx.x, lane = d & 31, wrp = d >> 5;
    float sc = pg[d] * rsqrtf(pv[d] + EPSB);
    s_scale[d] = sc;
    s_shift[d] = (pb[d] - pm[d]) * sc + pbt[d];
    if (d < NWD) kvw[d] = g_kvb[(t * BB + b) * NWD + d];
    sqw[d] = g_sq[((t * BB + b) * NN + n0) * NWD + d];   // 32 cols x 12 words, coalesced
    __syncthreads();

    if (d < 32) {  // decode q AND kv for column n0+d
        int c0 = 0;
#pragma unroll
        for (int w = 0; w < NWD; w++) {
            uint32_t m = sqw[d * NWD + w] & kvw[w];
            while (m) {
                slist[d][c0++] = (uint32_t)(((w << 5) + (__ffs(m) - 1)) * ROWB);
                m &= m - 1;
            }
        }
        scnt[d] = c0;
    }
    __syncthreads();

    const char* wTb = (const char*)g_wT[3];
    int dofs = d << 2;
    for (int nl = 0; nl < 32; nl++) {
        int cnt = scnt[nl];
        const uint32_t* L = slist[nl];
        float a0 = 0.f, a1 = 0.f, a2 = 0.f, a3 = 0.f;
        int i = 0;
        for (; i + 3 < cnt; i += 4) {
            a0 += *(const float*)(wTb + L[i]     + dofs);
            a1 += *(const float*)(wTb + L[i + 1] + dofs);
            a2 += *(const float*)(wTb + L[i + 2] + dofs);
            a3 += *(const float*)(wTb + L[i + 3] + dofs);
        }
        for (; i < cnt; i++) a0 += *(const float*)(wTb + L[i] + dofs);
        tile[nl * 385 + d] = (a0 + a1) + (a2 + a3);
    }
    __syncthreads();
    // coalesced write phase: warp wrp writes row dd, lanes = consecutive n
    for (int i = 0; i < 32; i++) {
        int dd = i * NWD + wrp;
        int idx = ((t * BB + b) * CC + dd) * NN + n0 + lane;
        out1[idx] = tile[lane * 385 + dd] * s_scale[dd] + s_shift[dd] + x[idx];
    }
}

// ---------------------------------------------------------------------------
extern "C" void kernel_launch(void* const* d_in, const int* in_sizes, int n_in,
                              void* d_out, int out_size)
{
    const float* x    = (const float*)d_in[0];
    const float* q_w  = (const float*)d_in[1];
    const float* q_g  = (const float*)d_in[2];
    const float* q_b  = (const float*)d_in[3];
    const float* q_m  = (const float*)d_in[4];
    const float* q_v  = (const float*)d_in[5];
    const float* k_w  = (const float*)d_in[6];
    const float* k_g  = (const float*)d_in[7];
    const float* k_b  = (const float*)d_in[8];
    const float* k_m  = (const float*)d_in[9];
    const float* k_v  = (const float*)d_in[10];
    const float* v_w  = (const float*)d_in[11];
    const float* v_g  = (const float*)d_in[12];
    const float* v_b  = (const float*)d_in[13];
    const float* v_m  = (const float*)d_in[14];
    const float* v_v  = (const float*)d_in[15];
    const float* p_w  = (const float*)d_in[16];
    const float* p_b  = (const float*)d_in[17];
    const float* p_g  = (const float*)d_in[18];
    const float* p_bt = (const float*)d_in[19];
    const float* p_m  = (const float*)d_in[20];
    const float* p_v  = (const float*)d_in[21];
    float* out = (float*)d_out;

    cudaFuncSetAttribute(proj_kernel, cudaFuncAttributeMaxDynamicSharedMemorySize, 32 * 385 * 4);

    transpose_kernel<<<dim3(12, 12, 4), dim3(32, 32)>>>(q_w, k_w, v_w, p_w);
    lif_x_kernel<<<dim3(12, 8, 32), 1024>>>(x);
    qkv_kernel<<<dim3(256, 32), 384>>>(q_g, q_b, q_m, q_v,
                                       k_g, k_b, k_m, k_v,
                                       v_g, v_b, v_m, v_v,
                                       out + OUT1_ELEMS);
    kvcount_kernel<<<dim3(32, 4, 8), 384>>>();
    kvlif_kernel<<<32, 384>>>();
    proj_kernel<<<dim3(8, 32, 4), 384, 32 * 385 * 4>>>(x, p_b, p_g, p_bt, p_m, p_v, out);
}